// round 14
// baseline (speedup 1.0000x reference)
#include <cuda_runtime.h>
#include <cstdint>

#define N_NODES   100000
#define D_FEAT    128
#define HID       64
#define N_SAMPLES 250000

// Dual-pipe split (measured solo rates: HMMA-tf32 105us, FFMA-f32x2 130us)
#define H_BLOCKS  433                 // x128 rows = 55424 (tensor pipe)
#define F_BLOCKS  349                 // x128 rows = 44672 (fma pipe)
#define H_ROWS    55424
#define H_GROUPS  3                   // ceil(433/148)
#define F_GROUPS  3                   // ceil(349/148)
#define GRID_TOT  ((H_GROUPS + F_GROUPS) * 148)   // 888, groups alternate H/F

// Merged per-node table (51.2 MB scratch).
// T[n][ 0: 64] = x1[n]@w1[0:128]   + x2[n]@w1[256:384] + b1   (src half)
// T[n][64:128] = x1[n]@w1[128:256] + x2[n]@w1[384:512]        (dst half)
__device__ float g_T[(size_t)N_NODES * 128];

// B operand, tf32-rounded fp32 (H path). Chunk-major: [c][n 0..127][kk 0..63].
__device__ float g_Bt[4 * 128 * 64];

__device__ int g_idx_is64;   // 1 if train_sample is int64, 0 if int32

// ---------------- helpers ----------------
__device__ __forceinline__ uint32_t f2tf32(float f) {
    uint32_t r;
    asm("cvt.rna.tf32.f32 %0, %1;" : "=r"(r) : "f"(f));
    return r;
}
__device__ __forceinline__ void mma_tf32(float& d0, float& d1, float& d2, float& d3,
                                         uint32_t a0, uint32_t a1, uint32_t a2, uint32_t a3,
                                         uint32_t b0, uint32_t b1) {
    asm volatile(
        "mma.sync.aligned.m16n8k8.row.col.f32.tf32.tf32.f32 "
        "{%0,%1,%2,%3}, {%4,%5,%6,%7}, {%8,%9}, {%0,%1,%2,%3};"
        : "+f"(d0), "+f"(d1), "+f"(d2), "+f"(d3)
        : "r"(a0), "r"(a1), "r"(a2), "r"(a3), "r"(b0), "r"(b1));
}
__device__ __forceinline__ unsigned long long pack2(float lo, float hi) {
    unsigned long long r;
    asm("mov.b64 %0, {%1,%2};" : "=l"(r) : "f"(lo), "f"(hi));
    return r;
}
__device__ __forceinline__ unsigned long long fma2(unsigned long long a,
                                                   unsigned long long b,
                                                   unsigned long long c) {
    unsigned long long d;
    asm("fma.rn.f32x2 %0, %1, %2, %3;" : "=l"(d) : "l"(a), "l"(b), "l"(c));
    return d;
}
__device__ __forceinline__ float2 unpack2(unsigned long long v) {
    float2 r;
    asm("mov.b64 {%0,%1}, %2;" : "=f"(r.x), "=f"(r.y) : "l"(v));
    return r;
}

// ============================================================================
// Kernel 0: dtype detect (block 0) + B tf32 convert (128 blocks, 1 elem/thr).
// ============================================================================
__global__ void prep_kernel(const unsigned int* __restrict__ ts32,
                            const float* __restrict__ w1)
{
    int t = threadIdx.x;

    if (blockIdx.x == 0) {
        __shared__ int nonzero;
        if (t == 0) nonzero = 0;
        __syncthreads();
        unsigned int acc = 0;
#pragma unroll
        for (int i = 0; i < 16; i++) acc |= ts32[2 * (t + 256 * i) + 1];
        if (acc) atomicOr(&nonzero, 1);
        __syncthreads();
        if (t == 0) g_idx_is64 = nonzero ? 0 : 1;
    }

    int idx = blockIdx.x * 256 + t;                // 0..32767
    int c  = idx >> 13;
    int n  = (idx >> 6) & 127;
    int kk = idx & 63;
    int gk = c * 64 + kk;
    int wrow = (n < 64) ? ((gk < 128) ? gk : gk + 128)
                        : ((gk < 128) ? gk + 128 : gk + 256);
    int wcol = n & 63;
    g_Bt[idx] = __uint_as_float(f2tf32(w1[wrow * HID + wcol]));
}

// ============================================================================
// Kernel 1: DUAL-PIPE grid-split GEMM.
// Groups of 148 bids alternate type; placement maps bid & bid+148 to the
// same SM -> wave 1 puts 1 HMMA CTA + 1 FFMA CTA on every SM. 98 KB dynamic
// smem forces exactly 2 CTAs/SM. Paths are disjoint top-level branches
// (disjoint register live ranges -> no spill under the 128-reg cap).
// ============================================================================
#define AS_STRIDE 68                   // H path: fp32/row 64 + 4 pad
#define SMEM_TOT  100352               // 98 KB: 2/SM fit, 3/SM don't

__global__ __launch_bounds__(256, 2)
void precompute_dual_kernel(const float* __restrict__ in1,
                            const float* __restrict__ in2,
                            const float* __restrict__ w1,
                            const float* __restrict__ b1)
{
    extern __shared__ char smem[];
    const int t   = threadIdx.x;
    const int bid = blockIdx.x;
    const int grp = bid / 148;
    const int slt = bid % 148;

    if ((grp & 1) == 0) {
        // ==================== H path: tf32 HMMA (R13-exact) ====================
        const int h = (grp >> 1) * 148 + slt;
        if (h >= H_BLOCKS) return;
        const int row0 = h * 128;

        float* Atf = (float*)smem;                 // 128 x 68 fp32 = 34816 B
        const int wid    = t >> 5;
        const int lane   = t & 31;
        const int warp_m = wid & 1;
        const int warp_n = wid >> 1;

        float acc[4][4][4];
#pragma unroll
        for (int mt = 0; mt < 4; mt++)
#pragma unroll
            for (int nt = 0; nt < 4; nt++)
#pragma unroll
                for (int r = 0; r < 4; r++) acc[mt][nt][r] = 0.f;

        const int arow = lane >> 2;
        const int acol = lane & 3;

        for (int c = 0; c < 4; c++) {
            if (c) __syncthreads();

            const float* __restrict__ in = (c < 2) ? in1 : in2;
            const int col0 = (c & 1) * 64;
#pragma unroll
            for (int i = 0; i < 8; i++) {
                int linear = t + 256 * i;
                int r  = linear >> 4;
                int c4 = linear & 15;
                int grow = row0 + r;               // < H_ROWS < N_NODES always
                float4 v = *(const float4*)&in[(size_t)grow * D_FEAT + col0 + 4 * c4];
                uint4 w;
                w.x = f2tf32(v.x); w.y = f2tf32(v.y);
                w.z = f2tf32(v.z); w.w = f2tf32(v.w);
                *(uint4*)&Atf[r * AS_STRIDE + 4 * c4] = w;
            }
            __syncthreads();

            const uint32_t* __restrict__ Au = (const uint32_t*)Atf;
            const uint32_t* __restrict__ Bu = (const uint32_t*)(g_Bt + c * 8192);

#pragma unroll
            for (int ks = 0; ks < 8; ks++) {
                const int k0 = ks * 8;
                uint32_t a[4][4];
#pragma unroll
                for (int mt = 0; mt < 4; mt++) {
                    int row = warp_m * 64 + mt * 16 + arow;
                    int base = row * AS_STRIDE + k0 + acol;
                    a[mt][0] = Au[base];
                    a[mt][1] = Au[base + 8 * AS_STRIDE];
                    a[mt][2] = Au[base + 4];
                    a[mt][3] = Au[base + 8 * AS_STRIDE + 4];
                }
                uint32_t b[4][2];
#pragma unroll
                for (int nt = 0; nt < 4; nt++) {
                    int n = warp_n * 32 + nt * 8 + arow;
                    int base = n * 64 + k0 + acol;
                    b[nt][0] = Bu[base];
                    b[nt][1] = Bu[base + 4];
                }
#pragma unroll
                for (int mt = 0; mt < 4; mt++)
#pragma unroll
                    for (int nt = 0; nt < 4; nt++) {
                        float* d = acc[mt][nt];
                        mma_tf32(d[0], d[1], d[2], d[3],
                                 a[mt][0], a[mt][1], a[mt][2], a[mt][3],
                                 b[nt][0], b[nt][1]);
                    }
            }
        }

        const int crow = lane >> 2;
        const int ccol = (lane & 3) * 2;
#pragma unroll
        for (int nt = 0; nt < 4; nt++) {
            int col = warp_n * 32 + nt * 8 + ccol;
            float2 bv = make_float2(0.f, 0.f);
            if (col < 64) bv = *(const float2*)&b1[col];
#pragma unroll
            for (int mt = 0; mt < 4; mt++) {
                int m = warp_m * 64 + mt * 16 + crow;
                int grow0 = row0 + m;
                int grow1 = grow0 + 8;
                float* d = acc[mt][nt];
                *(float2*)&g_T[(size_t)grow0 * 128 + col] =
                    make_float2(d[0] + bv.x, d[1] + bv.y);
                *(float2*)&g_T[(size_t)grow1 * 128 + col] =
                    make_float2(d[2] + bv.x, d[3] + bv.y);
            }
        }
    } else {
        // ==================== F path: packed-f32x2 FFMA (R3-exact) ============
        const int f = (grp >> 1) * 148 + slt;
        if (f >= F_BLOCKS) return;
        const int row0 = H_ROWS + f * 128;

        float* As = (float*)smem;                  // [128][64]
        float* Bs = (float*)smem + 128 * 64;       // [64][128]

        const int tm = t >> 4;
        const int tn = t & 15;
        const float4 bias = *(const float4*)&b1[tn * 4];

        unsigned long long acc[8][4];
#pragma unroll
        for (int i = 0; i < 8; i++)
#pragma unroll
            for (int j = 0; j < 4; j++) acc[i][j] = 0ULL;

        for (int ko = 0; ko < 256; ko += 64) {
            if (ko) __syncthreads();
            const float* __restrict__ in = (ko < 128) ? in1 : in2;
            const int col0 = ko & 127;

#pragma unroll
            for (int i = 0; i < 8; i++) {
                int linear = t + 256 * i;
                int r = linear >> 4;
                int c = linear & 15;
                int grow = row0 + r;
                float4 v = make_float4(0.f, 0.f, 0.f, 0.f);
                if (grow < N_NODES)
                    v = *(const float4*)&in[(size_t)grow * D_FEAT + col0 + 4 * c];
                *(float4*)&As[r * 64 + 4 * c] = v;
            }
#pragma unroll
            for (int i = 0; i < 8; i++) {
                int linear = t + 256 * i;
                int kk = linear >> 5;
                int c4 = linear & 31;
                int gk = ko + kk;
                int wrow, wcol;
                if (c4 < 16) { wrow = (gk < 128) ? gk : gk + 128; wcol = 4 * c4; }
                else         { wrow = (gk < 128) ? gk + 128 : gk + 256; wcol = 4 * (c4 - 16); }
                float4 v = *(const float4*)&w1[wrow * HID + wcol];
                *(float4*)&Bs[kk * 128 + 4 * c4] = v;
            }
            __syncthreads();

#pragma unroll
            for (int k = 0; k < 64; k += 2) {
                float2 af[8];
#pragma unroll
                for (int i = 0; i < 4; i++) {
                    af[i]     = *(const float2*)&As[(tm * 4 + i) * 64 + k];
                    af[i + 4] = *(const float2*)&As[(64 + tm * 4 + i) * 64 + k];
                }
#pragma unroll
                for (int kq = 0; kq < 2; kq++) {
                    ulonglong2 blo = *(const ulonglong2*)&Bs[(k + kq) * 128 + tn * 4];
                    ulonglong2 bhi = *(const ulonglong2*)&Bs[(k + kq) * 128 + 64 + tn * 4];
                    unsigned long long bp0 = blo.x, bp1 = blo.y;
                    unsigned long long bp2 = bhi.x, bp3 = bhi.y;
#pragma unroll
                    for (int i = 0; i < 8; i++) {
                        float a = kq ? af[i].y : af[i].x;
                        unsigned long long ap = pack2(a, a);
                        acc[i][0] = fma2(ap, bp0, acc[i][0]);
                        acc[i][1] = fma2(ap, bp1, acc[i][1]);
                        acc[i][2] = fma2(ap, bp2, acc[i][2]);
                        acc[i][3] = fma2(ap, bp3, acc[i][3]);
                    }
                }
            }
        }

#pragma unroll
        for (int i = 0; i < 8; i++) {
            int m = (i < 4) ? (tm * 4 + i) : (64 + tm * 4 + (i - 4));
            int grow = row0 + m;
            if (grow < N_NODES) {
                float2 c0 = unpack2(acc[i][0]);
                float2 c1 = unpack2(acc[i][1]);
                float2 c2 = unpack2(acc[i][2]);
                float2 c3 = unpack2(acc[i][3]);
                *(float4*)&g_T[(size_t)grow * 128 + tn * 4] =
                    make_float4(c0.x + bias.x, c0.y + bias.y,
                                c1.x + bias.z, c1.y + bias.w);
                *(float4*)&g_T[(size_t)grow * 128 + 64 + tn * 4] =
                    make_float4(c2.x, c2.y, c3.x, c3.y);
            }
        }
    }
}

// ============================================================================
// Kernel 2: gather + head. Half-warp per sample; lane l -> float4 of hidden.
// ============================================================================
__global__ __launch_bounds__(256)
void gather_kernel(const void* __restrict__ ts_raw,
                   const float* __restrict__ w2,
                   float* __restrict__ out, int n)
{
    int hs   = (blockIdx.x * blockDim.x + threadIdx.x) >> 4;
    int lane = threadIdx.x & 15;
    if (hs >= n) return;

    long long src, dst;
    if (g_idx_is64) {
        longlong2 sd = ((const longlong2*)ts_raw)[hs];
        src = sd.x; dst = sd.y;
    } else {
        int2 sd = ((const int2*)ts_raw)[hs];
        src = sd.x; dst = sd.y;
    }
    src = min(max(src, 0LL), (long long)(N_NODES - 1));
    dst = min(max(dst, 0LL), (long long)(N_NODES - 1));

    float4 s = *(const float4*)(g_T + (size_t)src * 128 + 4 * lane);
    float4 d = *(const float4*)(g_T + (size_t)dst * 128 + 64 + 4 * lane);
    float4 w = ((const float4*)w2)[lane];

    float p = fmaxf(s.x + d.x, 0.f) * w.x
            + fmaxf(s.y + d.y, 0.f) * w.y
            + fmaxf(s.z + d.z, 0.f) * w.z
            + fmaxf(s.w + d.w, 0.f) * w.w;

#pragma unroll
    for (int off = 8; off; off >>= 1)
        p += __shfl_xor_sync(0xffffffffu, p, off);

    if (lane == 0) out[hs] = p;
}

// ============================================================================
extern "C" void kernel_launch(void* const* d_in, const int* in_sizes, int n_in,
                              void* d_out, int out_size)
{
    const float* in1 = (const float*)d_in[0];      // (100000,128) f32
    const float* in2 = (const float*)d_in[1];      // (100000,128) f32
    const void*  ts  = d_in[2];                    // (250000,2) int32/int64
    const float* w1  = (const float*)d_in[3];      // (512,64) f32
    const float* b1  = (const float*)d_in[4];      // (64,)   f32
    const float* w2  = (const float*)d_in[5];      // (64,1)  f32
    float*       out = (float*)d_out;              // (250000,1) f32

    (void)in_sizes; (void)n_in; (void)out_size;

    prep_kernel<<<128, 256>>>((const unsigned int*)ts, w1);

    cudaFuncSetAttribute(precompute_dual_kernel,
                         cudaFuncAttributeMaxDynamicSharedMemorySize, SMEM_TOT);
    precompute_dual_kernel<<<GRID_TOT, 256, SMEM_TOT>>>(in1, in2, w1, b1);

    int samples_per_block = 256 / 16;   // 16 samples per 256-thread block
    int blocks = (N_SAMPLES + samples_per_block - 1) / samples_per_block;
    gather_kernel<<<blocks, 256>>>(ts, w2, out, N_SAMPLES);
}